// round 12
// baseline (speedup 1.0000x reference)
#include <cuda_runtime.h>
#include <cuda_bf16.h>

// Wav2Frames: out[b, c, f] = x[b, f*WINSTEP + c]
// x: (32, 1, 480000) fp32 -> out: (32, 400, 2998) fp32
//
// R12 = R10 (best: 34.4us kernel) + streaming cache hints ONLY.
//   __ldcs on the input stream (read exactly once),
//   __stcs on the output stream (written exactly once, never re-read):
//   evict-first policy stops the 153MB write stream churning L2 against
//   the read stream. Single-variable change on the best base.
// All else identical to R10: F_TILE=112, NTILES=27 (864 jobs ~ 97.3% of
// 3x296 slots), float4 LDG fill, smem skew j+(j>>5), per-row sector
// shift s(c)=(2c)&7, float2 frame-pair stores, 1024 threads, 2 CTAs/SM.

#define B        32
#define T        480000
#define WINLEN   400
#define WINSTEP  160
#define NFRAMES  2998
#define F_TILE   112
#define NTILES   27                                    // 27*112 = 3024 >= 2998
#define NPAIRS_T (F_TILE / 2)                          // 56 frame pairs
#define SPAN     ((F_TILE - 1) * WINSTEP + WINLEN + 6 * WINSTEP)  // 19120
#define SM_SZ    (SPAN + SPAN / 32 + 4)                // 19721 floats (~78.9 KB)
#define THREADS  1024

__global__ __launch_bounds__(THREADS, 2)
void wav2frames_kernel(const float* __restrict__ x, float* __restrict__ out) {
    extern __shared__ float sm[];

    const int tile = blockIdx.x;
    const int b    = blockIdx.y;
    const int tid  = threadIdx.x;
    const int lane = tid & 31;
    const int w    = tid >> 5;                         // 32 warps

    const int f0 = tile * F_TILE;                      // even
    const int x0 = f0 * WINSTEP;

    // ---- vectorized coalesced fill: gmem float4 (streaming) -> skewed smem ----
    const float* __restrict__ xb = x + (size_t)b * T + x0;
    const int span  = (x0 + SPAN <= T) ? SPAN : (T - x0);   // multiple of 4
    const int span4 = span >> 2;
    const float4* __restrict__ xb4 = reinterpret_cast<const float4*>(xb);

    for (int i4 = tid; i4 < span4; i4 += THREADS) {    // ~5 iterations
        const float4 v = __ldcs(xb4 + i4);
        const int i = i4 << 2;
        const int p = i + (i >> 5);                    // skew: j + (j>>5)
        sm[p + 0] = v.x;
        sm[p + 1] = v.y;
        sm[p + 2] = v.z;
        sm[p + 3] = v.w;
    }
    __syncthreads();

    float* __restrict__ outb = out + (size_t)b * WINLEN * NFRAMES;

    // ---- main store: 56 frame pairs x 16 c-groups, sector-aligned chunks ----
    const int q      = w & 1;
    const int cg     = w >> 1;                         // 0..15
    const int fp_idx = lane + 32 * q;                  // 0..63 (>=56 idle)
    const int fbase  = f0 + 2 * fp_idx;                // even
    const int jbase  = 2 * fp_idx * WINSTEP;           // 320 * fp_idx

    if (fp_idx < NPAIRS_T) {
        #pragma unroll 5
        for (int c = cg; c < WINLEN; c += 16) {        // 25 iterations
            const int s = (2 * c) & 7;                 // 0,2,4,6 (even)
            const int f = fbase + s;
            if (f <= NFRAMES - 2) {
                const int j0 = jbase + s * WINSTEP + c;
                const int j1 = j0 + WINSTEP;
                float2 v;
                v.x = sm[j0 + (j0 >> 5)];
                v.y = sm[j1 + (j1 >> 5)];
                __stcs(reinterpret_cast<float2*>(
                           outb + (size_t)c * NFRAMES + f), v);
            }
        }
    }

    // ---- head: tile 0 writes frames [0, s(c)) for each row c ----
    if (tile == 0) {
        for (int idx = tid; idx < WINLEN * 3; idx += THREADS) {
            const int c = idx / 3;
            const int m = idx - 3 * c;                 // pair slot 0..2
            const int s = (2 * c) & 7;
            if (2 * m < s) {
                const int fh = 2 * m;
                const int j0 = fh * WINSTEP + c;
                const int j1 = j0 + WINSTEP;
                float2 v;
                v.x = sm[j0 + (j0 >> 5)];
                v.y = sm[j1 + (j1 >> 5)];
                __stcs(reinterpret_cast<float2*>(
                           outb + (size_t)c * NFRAMES + fh), v);
            }
        }
    }
}

extern "C" void kernel_launch(void* const* d_in, const int* in_sizes, int n_in,
                              void* d_out, int out_size) {
    const float* x = (const float*)d_in[0];            // (32, 1, 480000) fp32
    // d_in[1] = W (identity, unused), d_in[2] = winstep (fixed 160, unused)
    float* out = (float*)d_out;                        // (32, 400, 2998) fp32

    static bool configured = false;
    if (!configured) {
        cudaFuncSetAttribute(wav2frames_kernel,
                             cudaFuncAttributeMaxDynamicSharedMemorySize,
                             SM_SZ * (int)sizeof(float));
        configured = true;
    }

    dim3 grid(NTILES, B);                              // 27 x 32 = 864 CTAs
    wav2frames_kernel<<<grid, THREADS, SM_SZ * sizeof(float)>>>(x, out);
}

// round 13
// speedup vs baseline: 1.0215x; 1.0215x over previous
#include <cuda_runtime.h>
#include <cuda_bf16.h>

// Wav2Frames: out[b, c, f] = x[b, f*WINSTEP + c]
// x: (32, 1, 480000) fp32 -> out: (32, 400, 2998) fp32
//
// R13 = R10 (confirmed best: 34.4us kernel) + hoisted tail check ONLY.
//   The f <= NFRAMES-2 guard is only live in the LAST frame tile
//   (tile 26: f can reach 3028 > 2996; tiles <= 25: max f = 2916).
//   Interior tiles now run a check-free store loop (-25 predicates/thread).
//   No change to traffic, scheduling, or access patterns.
// Base (R10): F_TILE=112, NTILES=27 (864 jobs = 97.3% of 3x296 slots),
// float4 LDG fill, smem skew j+(j>>5), per-row sector shift s(c)=(2c)&7
// (the confirmed RMW win), float2 frame-pair stores, 1024 thr, 2 CTAs/SM.
// NO cache hints (R12 proved __stcs/__ldcs hurt: L2 residency of the
// write stream enables neighbor-CTA boundary merges).

#define B        32
#define T        480000
#define WINLEN   400
#define WINSTEP  160
#define NFRAMES  2998
#define F_TILE   112
#define NTILES   27                                    // 27*112 = 3024 >= 2998
#define NPAIRS_T (F_TILE / 2)                          // 56 frame pairs
#define SPAN     ((F_TILE - 1) * WINSTEP + WINLEN + 6 * WINSTEP)  // 19120
#define SM_SZ    (SPAN + SPAN / 32 + 4)                // 19721 floats (~78.9 KB)
#define THREADS  1024

__global__ __launch_bounds__(THREADS, 2)
void wav2frames_kernel(const float* __restrict__ x, float* __restrict__ out) {
    extern __shared__ float sm[];

    const int tile = blockIdx.x;
    const int b    = blockIdx.y;
    const int tid  = threadIdx.x;
    const int lane = tid & 31;
    const int w    = tid >> 5;                         // 32 warps

    const int f0 = tile * F_TILE;                      // even
    const int x0 = f0 * WINSTEP;

    // ---- vectorized coalesced fill: gmem float4 -> skewed smem ----
    const float* __restrict__ xb = x + (size_t)b * T + x0;
    const int span  = (x0 + SPAN <= T) ? SPAN : (T - x0);   // multiple of 4
    const int span4 = span >> 2;
    const float4* __restrict__ xb4 = reinterpret_cast<const float4*>(xb);

    for (int i4 = tid; i4 < span4; i4 += THREADS) {    // ~5 iterations
        const float4 v = xb4[i4];
        const int i = i4 << 2;
        const int p = i + (i >> 5);                    // skew: j + (j>>5)
        sm[p + 0] = v.x;
        sm[p + 1] = v.y;
        sm[p + 2] = v.z;
        sm[p + 3] = v.w;
    }
    __syncthreads();

    float* __restrict__ outb = out + (size_t)b * WINLEN * NFRAMES;

    // ---- main store: 56 frame pairs x 16 c-groups, sector-aligned chunks ----
    const int q      = w & 1;
    const int cg     = w >> 1;                         // 0..15
    const int fp_idx = lane + 32 * q;                  // 0..63 (>=56 idle)
    const int fbase  = f0 + 2 * fp_idx;                // even
    const int jbase  = 2 * fp_idx * WINSTEP;           // 320 * fp_idx

    if (fp_idx < NPAIRS_T) {
        if (tile != NTILES - 1) {
            // interior tiles: guard provably true -> check-free loop
            #pragma unroll 5
            for (int c = cg; c < WINLEN; c += 16) {    // 25 iterations
                const int s = (2 * c) & 7;             // 0,2,4,6 (even)
                const int f = fbase + s;
                const int j0 = jbase + s * WINSTEP + c;
                const int j1 = j0 + WINSTEP;
                float2 v;
                v.x = sm[j0 + (j0 >> 5)];
                v.y = sm[j1 + (j1 >> 5)];
                *reinterpret_cast<float2*>(outb + (size_t)c * NFRAMES + f) = v;
            }
        } else {
            // last tile: keep the bound check
            #pragma unroll 5
            for (int c = cg; c < WINLEN; c += 16) {
                const int s = (2 * c) & 7;
                const int f = fbase + s;
                if (f <= NFRAMES - 2) {
                    const int j0 = jbase + s * WINSTEP + c;
                    const int j1 = j0 + WINSTEP;
                    float2 v;
                    v.x = sm[j0 + (j0 >> 5)];
                    v.y = sm[j1 + (j1 >> 5)];
                    *reinterpret_cast<float2*>(
                        outb + (size_t)c * NFRAMES + f) = v;
                }
            }
        }
    }

    // ---- head: tile 0 writes frames [0, s(c)) for each row c ----
    if (tile == 0) {
        for (int idx = tid; idx < WINLEN * 3; idx += THREADS) {
            const int c = idx / 3;
            const int m = idx - 3 * c;                 // pair slot 0..2
            const int s = (2 * c) & 7;
            if (2 * m < s) {
                const int fh = 2 * m;
                const int j0 = fh * WINSTEP + c;
                const int j1 = j0 + WINSTEP;
                float2 v;
                v.x = sm[j0 + (j0 >> 5)];
                v.y = sm[j1 + (j1 >> 5)];
                *reinterpret_cast<float2*>(outb + (size_t)c * NFRAMES + fh) = v;
            }
        }
    }
}

extern "C" void kernel_launch(void* const* d_in, const int* in_sizes, int n_in,
                              void* d_out, int out_size) {
    const float* x = (const float*)d_in[0];            // (32, 1, 480000) fp32
    // d_in[1] = W (identity, unused), d_in[2] = winstep (fixed 160, unused)
    float* out = (float*)d_out;                        // (32, 400, 2998) fp32

    static bool configured = false;
    if (!configured) {
        cudaFuncSetAttribute(wav2frames_kernel,
                             cudaFuncAttributeMaxDynamicSharedMemorySize,
                             SM_SZ * (int)sizeof(float));
        configured = true;
    }

    dim3 grid(NTILES, B);                              // 27 x 32 = 864 CTAs
    wav2frames_kernel<<<grid, THREADS, SM_SZ * sizeof(float)>>>(x, out);
}

// round 14
// speedup vs baseline: 1.0414x; 1.0195x over previous
#include <cuda_runtime.h>
#include <cuda_bf16.h>

// Wav2Frames: out[b, c, f] = x[b, f*WINSTEP + c]
// x: (32, 1, 480000) fp32 -> out: (32, 400, 2998) fp32
//
// R14 = R10 VERBATIM (confirmed session best: 34.4us kernel / 39.3us bench).
// Rationale: R11 (perfect packing), R12 (streaming hints), R13 (hoisted
// guards) each measured 1.2-1.8us WORSE despite neutral-or-better
// first-principles deltas -> we are at the noise floor of the R10 local
// optimum. Reconfirming the best configuration per rigor.md.
//
// Mechanics: F_TILE=112, NTILES=27 (864 jobs ~ 97.3% of 3x296 CTA slots,
// 2 CTAs/SM x 148 SMs), float4 LDG fill, smem skew j+(j>>5) (conflict-free
// STS, 2-way LDS), per-row sector shift s(c)=(2c)&7 (kills partial-sector
// DRAM RMW on the write stream), float2 frame-pair stores, 1024 threads.

#define B        32
#define T        480000
#define WINLEN   400
#define WINSTEP  160
#define NFRAMES  2998
#define F_TILE   112
#define NTILES   27                                    // 27*112 = 3024 >= 2998
#define NPAIRS_T (F_TILE / 2)                          // 56 frame pairs
#define SPAN     ((F_TILE - 1) * WINSTEP + WINLEN + 6 * WINSTEP)  // 19120
#define SM_SZ    (SPAN + SPAN / 32 + 4)                // 19721 floats (~78.9 KB)
#define THREADS  1024

__global__ __launch_bounds__(THREADS, 2)
void wav2frames_kernel(const float* __restrict__ x, float* __restrict__ out) {
    extern __shared__ float sm[];

    const int tile = blockIdx.x;
    const int b    = blockIdx.y;
    const int tid  = threadIdx.x;
    const int lane = tid & 31;
    const int w    = tid >> 5;                         // 32 warps

    const int f0 = tile * F_TILE;                      // even
    const int x0 = f0 * WINSTEP;

    // ---- vectorized coalesced fill: gmem float4 -> skewed smem ----
    const float* __restrict__ xb = x + (size_t)b * T + x0;
    const int span  = (x0 + SPAN <= T) ? SPAN : (T - x0);   // multiple of 4
    const int span4 = span >> 2;
    const float4* __restrict__ xb4 = reinterpret_cast<const float4*>(xb);

    for (int i4 = tid; i4 < span4; i4 += THREADS) {    // ~5 iterations
        const float4 v = xb4[i4];
        const int i = i4 << 2;
        const int p = i + (i >> 5);                    // skew: j + (j>>5)
        sm[p + 0] = v.x;
        sm[p + 1] = v.y;
        sm[p + 2] = v.z;
        sm[p + 3] = v.w;
    }
    __syncthreads();

    float* __restrict__ outb = out + (size_t)b * WINLEN * NFRAMES;

    // ---- main store: 56 frame pairs x 16 c-groups, sector-aligned chunks ----
    const int q      = w & 1;
    const int cg     = w >> 1;                         // 0..15
    const int fp_idx = lane + 32 * q;                  // 0..63 (>=56 idle)
    const int fbase  = f0 + 2 * fp_idx;                // even
    const int jbase  = 2 * fp_idx * WINSTEP;           // 320 * fp_idx

    if (fp_idx < NPAIRS_T) {
        #pragma unroll 5
        for (int c = cg; c < WINLEN; c += 16) {        // 25 iterations
            const int s = (2 * c) & 7;                 // 0,2,4,6 (even)
            const int f = fbase + s;
            if (f <= NFRAMES - 2) {
                const int j0 = jbase + s * WINSTEP + c;
                const int j1 = j0 + WINSTEP;
                float2 v;
                v.x = sm[j0 + (j0 >> 5)];
                v.y = sm[j1 + (j1 >> 5)];
                *reinterpret_cast<float2*>(outb + (size_t)c * NFRAMES + f) = v;
            }
        }
    }

    // ---- head: tile 0 writes frames [0, s(c)) for each row c ----
    if (tile == 0) {
        for (int idx = tid; idx < WINLEN * 3; idx += THREADS) {
            const int c = idx / 3;
            const int m = idx - 3 * c;                 // pair slot 0..2
            const int s = (2 * c) & 7;
            if (2 * m < s) {
                const int fh = 2 * m;
                const int j0 = fh * WINSTEP + c;
                const int j1 = j0 + WINSTEP;
                float2 v;
                v.x = sm[j0 + (j0 >> 5)];
                v.y = sm[j1 + (j1 >> 5)];
                *reinterpret_cast<float2*>(outb + (size_t)c * NFRAMES + fh) = v;
            }
        }
    }
}

extern "C" void kernel_launch(void* const* d_in, const int* in_sizes, int n_in,
                              void* d_out, int out_size) {
    const float* x = (const float*)d_in[0];            // (32, 1, 480000) fp32
    // d_in[1] = W (identity, unused), d_in[2] = winstep (fixed 160, unused)
    float* out = (float*)d_out;                        // (32, 400, 2998) fp32

    static bool configured = false;
    if (!configured) {
        cudaFuncSetAttribute(wav2frames_kernel,
                             cudaFuncAttributeMaxDynamicSharedMemorySize,
                             SM_SZ * (int)sizeof(float));
        configured = true;
    }

    dim3 grid(NTILES, B);                              // 27 x 32 = 864 CTAs
    wav2frames_kernel<<<grid, THREADS, SM_SZ * sizeof(float)>>>(x, out);
}